// round 10
// baseline (speedup 1.0000x reference)
#include <cuda_runtime.h>
#include <cuda_bf16.h>
#include <cstdint>

// B=8, L=4000, D=512, WINDOW=5.
// Identity: shift/unshift cancel -> per column c, sort consecutive 5-row
// windows whose start rows are ≡ c (mod 5), circular over L.
//
// R10: R9 double-buffered bulk-async pipeline + the missing
// cudaFuncSetAttribute(MaxDynamicSharedMemorySize) call (77.9KB > 48KB
// default cap was why R9 failed to launch). Each CTA processes NT=4
// consecutive tiles with 2 ping-pong smem buffers so a 39KB bulk load is
// always in flight while the current tile is sorted/stored.

#define LROWS 4000
#define DCOLS 512
#define ROWBYTES (DCOLS * 4)             // 2048
#define TROWS 10
#define SROWS (TROWS + 9)                // 19
#define NT 4                             // tiles per CTA
#define NTHREADS 512
#define FRAME_BYTES (SROWS * ROWBYTES)   // 38912
#define OUT_BYTES   (TROWS * ROWBYTES)   // 20480
#define SMEM_BYTES  (2 * FRAME_BYTES + 32)

#define CE(x, y) { float _lo = fminf(x, y); float _hi = fmaxf(x, y); x = _lo; y = _hi; }

__device__ __forceinline__ void bulk_load_tile(
    const float* vb, uint32_t dst, uint32_t mbar, int P)
{
    asm volatile("mbarrier.arrive.expect_tx.shared.b64 _, [%0], %1;"
                 :: "r"(mbar), "r"((uint32_t)FRAME_BYTES) : "memory");
    int gr0 = P - 4; if (gr0 < 0) gr0 += LROWS;
    int n1  = SROWS; if (gr0 + n1 > LROWS) n1 = LROWS - gr0;
    int n2  = SROWS - n1;
    const char* src1 = (const char*)(vb + (size_t)gr0 * DCOLS);
    asm volatile(
        "cp.async.bulk.shared::cta.global.mbarrier::complete_tx::bytes "
        "[%0], [%1], %2, [%3];"
        :: "r"(dst), "l"(src1), "r"((uint32_t)(n1 * ROWBYTES)), "r"(mbar)
        : "memory");
    if (n2 > 0) {
        asm volatile(
            "cp.async.bulk.shared::cta.global.mbarrier::complete_tx::bytes "
            "[%0], [%1], %2, [%3];"
            :: "r"(dst + (uint32_t)(n1 * ROWBYTES)), "l"((const char*)vb),
               "r"((uint32_t)(n2 * ROWBYTES)), "r"(mbar) : "memory");
    }
}

__device__ __forceinline__ void mbar_wait(uint32_t mbar, uint32_t phase)
{
    uint32_t done;
    asm volatile(
        "{\n\t.reg .pred p;\n\t"
        "mbarrier.try_wait.parity.acquire.cta.shared::cta.b64 p, [%1], %2;\n\t"
        "selp.b32 %0, 1, 0, p;\n\t}"
        : "=r"(done) : "r"(mbar), "r"(phase) : "memory");
    if (!done) {
        asm volatile(
            "{\n\t.reg .pred P1;\n\t"
            "WL_%=:\n\t"
            "mbarrier.try_wait.parity.acquire.cta.shared::cta.b64 P1, [%0], %1, 0x989680;\n\t"
            "@P1 bra.uni WD_%=;\n\t"
            "bra.uni WL_%=;\n\t"
            "WD_%=:\n\t}"
            :: "r"(mbar), "r"(phase) : "memory");
    }
}

__global__ __launch_bounds__(NTHREADS, 2)
void swd_pipe_kernel(const float* __restrict__ v, float* __restrict__ out) {
    extern __shared__ float sm[];                 // 2 frames + 2 mbarriers
    uint32_t smem_base;
    asm("{ .reg .u64 t; cvta.to.shared.u64 t, %1; cvt.u32.u64 %0, t; }"
        : "=r"(smem_base) : "l"(sm));
    const uint32_t mb0 = smem_base + 2 * FRAME_BYTES;
    const uint32_t mb1 = mb0 + 8;

    const int tx    = threadIdx.x;                // column 0..511
    const int tile0 = blockIdx.x * NT;            // first tile of this CTA
    const int b     = blockIdx.y;                 // batch 0..7

    const float* __restrict__ vb = v   + (size_t)b * LROWS * DCOLS;
    float*       __restrict__ ob = out + (size_t)b * LROWS * DCOLS;

    if (tx == 0) {
        asm volatile("mbarrier.init.shared.b64 [%0], 1;" :: "r"(mb0) : "memory");
        asm volatile("mbarrier.init.shared.b64 [%0], 1;" :: "r"(mb1) : "memory");
    }
    __syncthreads();

    // Prime the pipeline: loads for tiles 0 and 1 in flight immediately.
    if (tx == 0) {
        bulk_load_tile(vb, smem_base,               mb0, tile0 * TROWS);
        bulk_load_tile(vb, smem_base + FRAME_BYTES, mb1, (tile0 + 1) * TROWS);
    }

    const int o = (tx + 4) % 5;                   // per-column window phase

    #pragma unroll
    for (int t = 0; t < NT; t++) {
        const int      buf   = t & 1;
        const uint32_t mbar  = buf ? mb1 : mb0;
        const uint32_t phase = (t >> 1) & 1;
        const uint32_t sbase = smem_base + buf * FRAME_BYTES;
        float* sb = sm + buf * (FRAME_BYTES / 4);
        const int P = (tile0 + t) * TROWS;

        mbar_wait(mbar, phase);

        // Sort column tx: windows at frame rows o, o+5, o+10 (in place).
        #pragma unroll
        for (int m = 0; m < 3; m++) {
            int base = (o + 5 * m) * DCOLS + tx;
            float a0 = sb[base];
            float a1 = sb[base + 1 * DCOLS];
            float a2 = sb[base + 2 * DCOLS];
            float a3 = sb[base + 3 * DCOLS];
            float a4 = sb[base + 4 * DCOLS];
            CE(a0, a1); CE(a3, a4); CE(a2, a4);
            CE(a2, a3); CE(a0, a3); CE(a0, a2);
            CE(a1, a4); CE(a1, a3); CE(a1, a2);
            sb[base]             = a0;
            sb[base + 1 * DCOLS] = a1;
            sb[base + 2 * DCOLS] = a2;
            sb[base + 3 * DCOLS] = a3;
            sb[base + 4 * DCOLS] = a4;
        }
        __syncthreads();

        if (tx == 0) {
            asm volatile("fence.proxy.async.shared::cta;" ::: "memory");
            char* dst = (char*)(ob + (size_t)P * DCOLS);
            asm volatile(
                "cp.async.bulk.global.shared::cta.bulk_group [%0], [%1], %2;"
                :: "l"(dst), "r"(sbase + 4 * ROWBYTES), "r"((uint32_t)OUT_BYTES)
                : "memory");
            asm volatile("cp.async.bulk.commit_group;" ::: "memory");
            if (t + 2 < NT) {
                // Buffer reuse: the store just issued FROM this buffer must
                // drain before the next load overwrites it.
                asm volatile("cp.async.bulk.wait_group 0;" ::: "memory");
                bulk_load_tile(vb, sbase, mbar, (tile0 + t + 2) * TROWS);
            }
        }
    }

    if (tx == 0) {
        asm volatile("cp.async.bulk.wait_group 0;" ::: "memory");
    }
}

extern "C" void kernel_launch(void* const* d_in, const int* in_sizes, int n_in,
                              void* d_out, int out_size) {
    const float* v = (const float*)d_in[2];   // inputs: q (unused), k (unused), v
    float* out     = (float*)d_out;

    cudaFuncSetAttribute(swd_pipe_kernel,
                         cudaFuncAttributeMaxDynamicSharedMemorySize, SMEM_BYTES);

    dim3 grid((LROWS / TROWS) / NT, 8);       // 100 x 8 = 800 CTAs
    swd_pipe_kernel<<<grid, NTHREADS, SMEM_BYTES>>>(v, out);
}

// round 11
// speedup vs baseline: 1.0593x; 1.0593x over previous
#include <cuda_runtime.h>
#include <cuda_bf16.h>
#include <cstdint>

// B=8, L=4000, D=512, WINDOW=5.
// Identity: shift/unshift cancel -> per column c, sort consecutive 5-row
// windows whose start rows are ≡ c (mod 5), circular over L.
//
// R11: ring-buffer persistent CTAs. R5-R10 all pinned at ~21.3us profile with
// every unit <=52%: the binder is the chip-wide LTS byte-throughput cap, and
// the halo re-reads (1.9x read amplification) were pure overhead on it.
// Each CTA owns a chunk of consecutive tiles and a 40-row smem ring
// (ring row = global row mod 40): steady tiles bulk-load only their 10 NEW
// rows; the 9-row overlap is reused in place. Sorted straddling windows are
// shared between tiles (idempotent sort). Traffic 190 -> ~136 MB.

#define LROWS 4000
#define DCOLS 512
#define ROWBYTES (DCOLS * 4)        // 2048
#define TROWS 10
#define RING 40
#define NTILES (LROWS / TROWS)      // 400 per batch
#define GPB 37                      // CTAs per batch: 37*8 = 296 = one wave
#define NTHREADS 512
#define SMEM_BYTES (RING * ROWBYTES + 64)   // ring + 4 mbarriers

#define CE(x, y) { float _lo = fminf(x, y); float _hi = fmaxf(x, y); x = _lo; y = _hi; }

// Load rows [first, first+n) (unwrapped coords) into ring rows (r mod 40),
// 1 bulk copy per row (2KB). tx0 only. Single expect_tx for the whole batch.
__device__ __forceinline__ void load_rows(const float* vb, int first, int n,
                                          uint32_t ring_base, uint32_t mbar)
{
    asm volatile("mbarrier.arrive.expect_tx.shared.b64 _, [%0], %1;"
                 :: "r"(mbar), "r"((uint32_t)(n * ROWBYTES)) : "memory");
    for (int r = first; r < first + n; r++) {
        int gs = r; if (gs < 0) gs += LROWS; else if (gs >= LROWS) gs -= LROWS;
        int rr = r % RING; if (rr < 0) rr += RING;
        asm volatile(
            "cp.async.bulk.shared::cta.global.mbarrier::complete_tx::bytes "
            "[%0], [%1], %2, [%3];"
            :: "r"(ring_base + (uint32_t)(rr * ROWBYTES)),
               "l"((const char*)(vb + (size_t)gs * DCOLS)),
               "r"((uint32_t)ROWBYTES), "r"(mbar) : "memory");
    }
}

__device__ __forceinline__ void mbar_wait(uint32_t mbar, uint32_t phase)
{
    uint32_t done;
    asm volatile(
        "{\n\t.reg .pred p;\n\t"
        "mbarrier.try_wait.parity.acquire.cta.shared::cta.b64 p, [%1], %2;\n\t"
        "selp.b32 %0, 1, 0, p;\n\t}"
        : "=r"(done) : "r"(mbar), "r"(phase) : "memory");
    if (!done) {
        asm volatile(
            "{\n\t.reg .pred P1;\n\t"
            "WL_%=:\n\t"
            "mbarrier.try_wait.parity.acquire.cta.shared::cta.b64 P1, [%0], %1, 0x989680;\n\t"
            "@P1 bra.uni WD_%=;\n\t"
            "bra.uni WL_%=;\n\t"
            "WD_%=:\n\t}"
            :: "r"(mbar), "r"(phase) : "memory");
    }
}

// Sort the 5-row window starting at unwrapped row s, column tx, in the ring.
__device__ __forceinline__ void sort_win(float* sm, int s, int tx)
{
    int r0 = s % RING; if (r0 < 0) r0 += RING;
    int r1 = r0 + 1; if (r1 >= RING) r1 -= RING;
    int r2 = r1 + 1; if (r2 >= RING) r2 -= RING;
    int r3 = r2 + 1; if (r3 >= RING) r3 -= RING;
    int r4 = r3 + 1; if (r4 >= RING) r4 -= RING;
    float a0 = sm[r0 * DCOLS + tx];
    float a1 = sm[r1 * DCOLS + tx];
    float a2 = sm[r2 * DCOLS + tx];
    float a3 = sm[r3 * DCOLS + tx];
    float a4 = sm[r4 * DCOLS + tx];
    CE(a0, a1); CE(a3, a4); CE(a2, a4);
    CE(a2, a3); CE(a0, a3); CE(a0, a2);
    CE(a1, a4); CE(a1, a3); CE(a1, a2);
    sm[r0 * DCOLS + tx] = a0;
    sm[r1 * DCOLS + tx] = a1;
    sm[r2 * DCOLS + tx] = a2;
    sm[r3 * DCOLS + tx] = a3;
    sm[r4 * DCOLS + tx] = a4;
}

__global__ __launch_bounds__(NTHREADS, 2)
void swd_ring_kernel(const float* __restrict__ v, float* __restrict__ out) {
    extern __shared__ float sm[];
    uint32_t smem_base;
    asm("{ .reg .u64 t; cvta.to.shared.u64 t, %1; cvt.u32.u64 %0, t; }"
        : "=r"(smem_base) : "l"(sm));
    const uint32_t mbb = smem_base + RING * ROWBYTES;   // 4 mbarriers @ +0,8,16,24

    const int tx = threadIdx.x;                 // column 0..511
    const int g  = blockIdx.x;                  // chunk within batch
    const int b  = blockIdx.y;                  // batch

    const int t0 = (g * NTILES) / GPB;          // first tile (inclusive)
    const int t1 = ((g + 1) * NTILES) / GPB;    // last tile (exclusive)
    const int n  = t1 - t0;                     // 10 or 11
    const int P0 = t0 * TROWS;

    const float* __restrict__ vb = v   + (size_t)b * LROWS * DCOLS;
    float*       __restrict__ ob = out + (size_t)b * LROWS * DCOLS;

    if (tx == 0) {
        #pragma unroll
        for (int j = 0; j < 4; j++)
            asm volatile("mbarrier.init.shared.b64 [%0], 1;"
                         :: "r"(mbb + 8u * j) : "memory");
    }
    __syncthreads();

    // Prime: full 19-row frame for tile 0; 10 new rows for tile 1.
    if (tx == 0) {
        load_rows(vb, P0 - 4, 19, smem_base, mbb + 0);
        if (n > 1) load_rows(vb, P0 + 15, 10, smem_base, mbb + 8);
    }

    const int o = (tx + 4) % 5;                 // per-column window phase

    for (int i = 0; i < n; i++) {
        const int P = P0 + i * TROWS;
        mbar_wait(mbb + 8u * (i & 3), (i >> 2) & 1);

        // First tile of the chunk also sorts the lower straddling window;
        // steady tiles inherit it (already sorted by the previous tile).
        if (i == 0) sort_win(sm, P - 4 + o, tx);
        sort_win(sm, P + 1 + o, tx);
        sort_win(sm, P + 6 + o, tx);
        __syncthreads();

        if (tx == 0) {
            asm volatile("fence.proxy.async.shared::cta;" ::: "memory");
            asm volatile(
                "cp.async.bulk.global.shared::cta.bulk_group [%0], [%1], %2;"
                :: "l"((char*)(ob + (size_t)P * DCOLS)),
                   "r"(smem_base + (uint32_t)((P % RING) * ROWBYTES)),
                   "r"((uint32_t)(TROWS * ROWBYTES)) : "memory");
            asm volatile("cp.async.bulk.commit_group;" ::: "memory");
            if (i + 2 < n) {
                // Store i-1 must drain before its ring rows are overwritten.
                asm volatile("cp.async.bulk.wait_group 1;" ::: "memory");
                load_rows(vb, P + 25, 10, smem_base, mbb + 8u * ((i + 2) & 3));
            }
        }
        // NOTE: no syncthreads needed here; next iteration's mbar_wait and
        // sort touch rows disjoint from the outstanding store (proven bounds).
    }

    if (tx == 0) {
        asm volatile("cp.async.bulk.wait_group 0;" ::: "memory");
    }
}

extern "C" void kernel_launch(void* const* d_in, const int* in_sizes, int n_in,
                              void* d_out, int out_size) {
    const float* v = (const float*)d_in[2];   // inputs: q (unused), k (unused), v
    float* out     = (float*)d_out;

    cudaFuncSetAttribute(swd_ring_kernel,
                         cudaFuncAttributeMaxDynamicSharedMemorySize, SMEM_BYTES);

    dim3 grid(GPB, 8);                        // 37 x 8 = 296 CTAs = one wave
    swd_ring_kernel<<<grid, NTHREADS, SMEM_BYTES>>>(v, out);
}

// round 12
// speedup vs baseline: 1.1653x; 1.1000x over previous
#include <cuda_runtime.h>
#include <cuda_bf16.h>
#include <cstdint>

// B=8, L=4000, D=512, WINDOW=5.
// Identity: shift/unshift cancel -> per column c, sort consecutive 5-row
// windows whose start rows are ≡ c (mod 5), circular over L.
//
// R12: R11 ring-buffer persistent kernel + L2 CACHE POLICY HINTS.
// Evidence: measured DRAM traffic ~87MB at a pinned ~4.2TB/s effective rate;
// footprint (131MB) > L2 (126MB) so output writes evict the input each
// replay, forcing mixed R/W DRAM streams. Loads use L2::evict_last (pin the
// 65.5MB input in L2), stores use L2::evict_first (stream output through a
// small slice). Target steady state: reads all L2 hits, DRAM ~= writes only.

#define LROWS 4000
#define DCOLS 512
#define ROWBYTES (DCOLS * 4)        // 2048
#define TROWS 10
#define RING 40
#define NTILES (LROWS / TROWS)      // 400 per batch
#define GPB 37                      // CTAs per batch: 37*8 = 296 = one wave
#define NTHREADS 512
#define SMEM_BYTES (RING * ROWBYTES + 64)   // ring + 4 mbarriers

#define CE(x, y) { float _lo = fminf(x, y); float _hi = fmaxf(x, y); x = _lo; y = _hi; }

// Load rows [first, first+n) (unwrapped coords) into ring rows (r mod 40),
// one 2KB bulk copy per row, with evict_last policy. tx0 only.
__device__ __forceinline__ void load_rows(const float* vb, int first, int n,
                                          uint32_t ring_base, uint32_t mbar,
                                          uint64_t pol_last)
{
    asm volatile("mbarrier.arrive.expect_tx.shared.b64 _, [%0], %1;"
                 :: "r"(mbar), "r"((uint32_t)(n * ROWBYTES)) : "memory");
    for (int r = first; r < first + n; r++) {
        int gs = r; if (gs < 0) gs += LROWS; else if (gs >= LROWS) gs -= LROWS;
        int rr = r % RING; if (rr < 0) rr += RING;
        asm volatile(
            "cp.async.bulk.shared::cta.global.mbarrier::complete_tx::bytes"
            ".L2::cache_hint [%0], [%1], %2, [%3], %4;"
            :: "r"(ring_base + (uint32_t)(rr * ROWBYTES)),
               "l"((const char*)(vb + (size_t)gs * DCOLS)),
               "r"((uint32_t)ROWBYTES), "r"(mbar), "l"(pol_last) : "memory");
    }
}

__device__ __forceinline__ void mbar_wait(uint32_t mbar, uint32_t phase)
{
    uint32_t done;
    asm volatile(
        "{\n\t.reg .pred p;\n\t"
        "mbarrier.try_wait.parity.acquire.cta.shared::cta.b64 p, [%1], %2;\n\t"
        "selp.b32 %0, 1, 0, p;\n\t}"
        : "=r"(done) : "r"(mbar), "r"(phase) : "memory");
    if (!done) {
        asm volatile(
            "{\n\t.reg .pred P1;\n\t"
            "WL_%=:\n\t"
            "mbarrier.try_wait.parity.acquire.cta.shared::cta.b64 P1, [%0], %1, 0x989680;\n\t"
            "@P1 bra.uni WD_%=;\n\t"
            "bra.uni WL_%=;\n\t"
            "WD_%=:\n\t}"
            :: "r"(mbar), "r"(phase) : "memory");
    }
}

// Sort the 5-row window starting at unwrapped row s, column tx, in the ring.
__device__ __forceinline__ void sort_win(float* sm, int s, int tx)
{
    int r0 = s % RING; if (r0 < 0) r0 += RING;
    int r1 = r0 + 1; if (r1 >= RING) r1 -= RING;
    int r2 = r1 + 1; if (r2 >= RING) r2 -= RING;
    int r3 = r2 + 1; if (r3 >= RING) r3 -= RING;
    int r4 = r3 + 1; if (r4 >= RING) r4 -= RING;
    float a0 = sm[r0 * DCOLS + tx];
    float a1 = sm[r1 * DCOLS + tx];
    float a2 = sm[r2 * DCOLS + tx];
    float a3 = sm[r3 * DCOLS + tx];
    float a4 = sm[r4 * DCOLS + tx];
    CE(a0, a1); CE(a3, a4); CE(a2, a4);
    CE(a2, a3); CE(a0, a3); CE(a0, a2);
    CE(a1, a4); CE(a1, a3); CE(a1, a2);
    sm[r0 * DCOLS + tx] = a0;
    sm[r1 * DCOLS + tx] = a1;
    sm[r2 * DCOLS + tx] = a2;
    sm[r3 * DCOLS + tx] = a3;
    sm[r4 * DCOLS + tx] = a4;
}

__global__ __launch_bounds__(NTHREADS, 2)
void swd_ring_kernel(const float* __restrict__ v, float* __restrict__ out) {
    extern __shared__ float sm[];
    uint32_t smem_base;
    asm("{ .reg .u64 t; cvta.to.shared.u64 t, %1; cvt.u32.u64 %0, t; }"
        : "=r"(smem_base) : "l"(sm));
    const uint32_t mbb = smem_base + RING * ROWBYTES;   // 4 mbarriers

    const int tx = threadIdx.x;                 // column 0..511
    const int g  = blockIdx.x;                  // chunk within batch
    const int b  = blockIdx.y;                  // batch

    const int t0 = (g * NTILES) / GPB;          // first tile (inclusive)
    const int t1 = ((g + 1) * NTILES) / GPB;    // last tile (exclusive)
    const int n  = t1 - t0;                     // 10 or 11
    const int P0 = t0 * TROWS;

    const float* __restrict__ vb = v   + (size_t)b * LROWS * DCOLS;
    float*       __restrict__ ob = out + (size_t)b * LROWS * DCOLS;

    // L2 policies: pin input (evict_last), stream output (evict_first).
    uint64_t pol_last, pol_first;
    asm volatile("createpolicy.fractional.L2::evict_last.b64 %0, 1.0;"
                 : "=l"(pol_last));
    asm volatile("createpolicy.fractional.L2::evict_first.b64 %0, 1.0;"
                 : "=l"(pol_first));

    if (tx == 0) {
        #pragma unroll
        for (int j = 0; j < 4; j++)
            asm volatile("mbarrier.init.shared.b64 [%0], 1;"
                         :: "r"(mbb + 8u * j) : "memory");
    }
    __syncthreads();

    // Prime: full 19-row frame for tile 0; 10 new rows for tile 1.
    if (tx == 0) {
        load_rows(vb, P0 - 4, 19, smem_base, mbb + 0, pol_last);
        if (n > 1) load_rows(vb, P0 + 15, 10, smem_base, mbb + 8, pol_last);
    }

    const int o = (tx + 4) % 5;                 // per-column window phase

    for (int i = 0; i < n; i++) {
        const int P = P0 + i * TROWS;
        mbar_wait(mbb + 8u * (i & 3), (i >> 2) & 1);

        // First tile of the chunk also sorts the lower straddling window;
        // steady tiles inherit it (already sorted by the previous tile).
        if (i == 0) sort_win(sm, P - 4 + o, tx);
        sort_win(sm, P + 1 + o, tx);
        sort_win(sm, P + 6 + o, tx);
        __syncthreads();

        if (tx == 0) {
            asm volatile("fence.proxy.async.shared::cta;" ::: "memory");
            asm volatile(
                "cp.async.bulk.global.shared::cta.bulk_group"
                ".L2::cache_hint [%0], [%1], %2, %3;"
                :: "l"((char*)(ob + (size_t)P * DCOLS)),
                   "r"(smem_base + (uint32_t)((P % RING) * ROWBYTES)),
                   "r"((uint32_t)(TROWS * ROWBYTES)), "l"(pol_first)
                : "memory");
            asm volatile("cp.async.bulk.commit_group;" ::: "memory");
            if (i + 2 < n) {
                // Store i-1 must drain before its ring rows are overwritten.
                asm volatile("cp.async.bulk.wait_group 1;" ::: "memory");
                load_rows(vb, P + 25, 10, smem_base,
                          mbb + 8u * ((i + 2) & 3), pol_last);
            }
        }
    }

    if (tx == 0) {
        asm volatile("cp.async.bulk.wait_group 0;" ::: "memory");
    }
}

extern "C" void kernel_launch(void* const* d_in, const int* in_sizes, int n_in,
                              void* d_out, int out_size) {
    const float* v = (const float*)d_in[2];   // inputs: q (unused), k (unused), v
    float* out     = (float*)d_out;

    cudaFuncSetAttribute(swd_ring_kernel,
                         cudaFuncAttributeMaxDynamicSharedMemorySize, SMEM_BYTES);

    dim3 grid(GPB, 8);                        // 37 x 8 = 296 CTAs = one wave
    swd_ring_kernel<<<grid, NTHREADS, SMEM_BYTES>>>(v, out);
}